// round 7
// baseline (speedup 1.0000x reference)
#include <cuda_runtime.h>
#include <math.h>

static constexpr int T_STEPS = 1460;
static constexpr int G_NUM   = 5000;
static constexpr int UH_L    = 15;
static constexpr int PF      = 10;   // 1460 % 10 == 0; lead ≈ 10 steps ≈ ~900 cyc > DRAM lat

__global__ void __launch_bounds__(32) hmets_kernel(
    const float* __restrict__ x_phy,     // (T, G, 3)
    const float* __restrict__ params,    // (T, G, 20) -- only t = T-1 used
    float* __restrict__ out)             // (T, G)
{
    const int g = blockIdx.x * blockDim.x + threadIdx.x;
    if (g >= G_NUM) return;

    // ---------------- parameters ----------------
    const float* pp = params + ((long long)(T_STEPS - 1) * G_NUM + g) * 20;
    float r[20];
#pragma unroll
    for (int i = 0; i < 20; i++) r[i] = 1.0f / (1.0f + expf(-pp[i]));

    const float ddf_min = r[0]  * 20.0f;
    const float ddf_pls = r[1]  * 20.0f;
    const float Tbm     = -2.0f  + r[2]  * 5.0f;
    const float Kcum    = 0.01f  + r[3]  * 0.19f;
    const float fcmin   = r[4]  * 0.1f;
    const float fcminp  = 0.01f  + r[5]  * 0.24f;
    const float Ccum    = 0.005f + r[6]  * 0.045f;
    const float Tbf     = -5.0f  + r[7]  * 7.0f;
    const float Kf      = r[8]  * 5.0f;
    const float exp_fe  = r[9];
    const float ET_eff  = r[10] * 3.0f;
    const float c_run   = r[11];
    const float c_v2p   = 1e-5f  + r[12] * (0.02f - 1e-5f);
    const float c_vad   = r[13] * 0.1f;
    const float c_phr   = 1e-5f  + r[14] * (0.01f - 1e-5f);
    const float Vmax    = 0.001f + r[15] * (500.0f - 0.001f);

    const float a1 = 0.3f  + r[16] * (20.0f - 0.3f);
    const float b1 = 0.01f + r[17] * (5.0f  - 0.01f);
    const float a2 = 0.5f  + r[18] * (13.0f - 0.5f);
    const float b2 = 0.15f + r[19] * (1.5f  - 0.15f);

    // fused constants (off the critical path)
    const float ddf_cap = ddf_min + ddf_pls;    // cap for ddf
    const float ddfK    = ddf_min * Kcum;       // ddf = min(cap, fma(ddfK, C, ddf_min))
    const float fcsum   = fcmin + fcminp;
    const float nfcC    = -fcsum * Ccum;        // wrf = max(fma(C, nfcC, fcsum), fcmin)
    const float invVmax = 1.0f / Vmax;

    // ---------------- gamma unit hydrographs ----------------
    float uh1[UH_L], uh2[UH_L];
    {
        float s1 = 0.0f, s2 = 0.0f;
#pragma unroll
        for (int l = 0; l < UH_L; l++) {
            float tt = (float)l + 0.5f;
            float w1 = powf(tt, a1 - 1.0f) * expf(-tt / b1);
            float w2 = powf(tt, a2 - 1.0f) * expf(-tt / b2);
            uh1[l] = w1; uh2[l] = w2; s1 += w1; s2 += w2;
        }
        const float i1 = 1.0f / s1, i2 = 1.0f / s2;
#pragma unroll
        for (int l = 0; l < UH_L; l++) { uh1[l] *= i1; uh2[l] *= i2; }
    }

    // ---------------- state + conv shift-register ----------------
    float S = 1e-5f, W = 1e-5f, C = 1e-5f, V = 0.5f * Vmax, P = 1e-5f;
    float acc[UH_L];
#pragma unroll
    for (int l = 0; l < UH_L; l++) acc[l] = 0.0f;

    // ------- forcing prefetch ring; slots hold FORCING-DERIVED values -------
    // (everything that depends only on forcing is computed at prefetch time,
    //  off the state dependency chain)
    const float* xb = x_phy + (long long)g * 3;
    float brn[PF], bsn[PF], bpf[PF], bmm[PF], bre[PF];
#pragma unroll
    for (int j = 0; j < PF; j++) {
        const float* q = xb + (long long)j * (3LL * G_NUM);
        const float Pp = q[0], Tt = q[1], PE = q[2];
        brn[j] = (Tt >= 0.0f) ? Pp : 0.0f;                                // rain
        bsn[j] = (Tt <  0.0f) ? Pp : 0.0f;                                // snow
        bpf[j] = Kf * __powf(fmaxf(Tbf - Tt, 1e-5f), exp_fe);             // pot_fr
        bmm[j] = Tt - Tbm;                                                // melt arg
        bre[j] = ET_eff * PE;                                             // RET
    }
    float* ob = out + g;

    for (int tb = 0; tb < T_STEPS; tb += PF) {
#pragma unroll
        for (int j = 0; j < PF; j++) {
            const int t = tb + j;
            const float rain  = brn[j], snow = bsn[j], potfr = bpf[j],
                        mm    = bmm[j], RET  = bre[j];

            // prefetch + derive row t+PF into the consumed slot
            const int t2 = t + PF;
            if (t2 < T_STEPS) {
                const float* q = xb + (long long)t2 * (3LL * G_NUM);
                const float Pp = q[0], Tt = q[1], PE = q[2];
                brn[j] = (Tt >= 0.0f) ? Pp : 0.0f;
                bsn[j] = (Tt <  0.0f) ? Pp : 0.0f;
                bpf[j] = Kf * __powf(fmaxf(Tbf - Tt, 1e-5f), exp_fe);
                bmm[j] = Tt - Tbm;
                bre[j] = ET_eff * PE;
            }

            // -------- HMETS step, minimized critical path --------
            const float fr      = fminf(potfr, W);
            const float Wm      = W - fr;
            const float ddf     = fminf(ddf_cap, fmaf(ddfK, C, ddf_min));   // off main chain (C only)
            const float meltcap = fmaxf(ddf * mm, 0.0f);
            const float S1      = S + fr;
            const float Ssn     = S1 + snow;
            const float melt    = fminf(meltcap, Ssn);
            S = Ssn - melt;
            C = (S > 1e-5f) ? (C + melt) : 0.0f;

            const float wrf  = fmaxf(fmaf(C, nfcC, fcsum), fcmin);
            const float wr   = wrf * S;
            const float wtmp = Wm + melt + rain;
            const float wa   = fmaxf(wtmp - wr, 0.0f);
            W = fminf(wtmp, wr);          // == (wa>0 ? wr : wtmp), wr >= 0

            const float ratio = V * invVmax;      // parallel side-chain off V
            const float crr   = c_run * ratio;
            const float crr2  = crr * ratio;
            const float omc2  = 1.0f - crr2;
            const float ht2   = c_vad * V;
            const float v2p   = c_v2p * V;
            const float Vbase = (V - ht2) - v2p;

            const float ht0   = crr * wa;
            const float infil = fmaxf((wa - RET) - ht0, 0.0f);
            const float V2    = fmaf(infil, omc2, Vbase);  // V + (infil - ht1) - ht2 - v2p
            const float Vn    = fminf(V2, Vmax);
            const float over  = V2 - Vn;
            V = Vn;
            const float ht1   = fmaf(crr2, infil, over);   // ht1 + over

            P = P + v2p;
            const float ht3 = c_phr * P;
            P = P - ht3;

            // -------- fused UH convolution (scatter) + output --------
            ob[(long long)t * G_NUM] = acc[0] + ht0 * uh1[0] + ht1 * uh2[0] + (ht2 + ht3);
#pragma unroll
            for (int l = 0; l < UH_L - 1; l++)
                acc[l] = acc[l + 1] + ht0 * uh1[l + 1] + ht1 * uh2[l + 1];
            acc[UH_L - 1] = 0.0f;
        }
    }
}

extern "C" void kernel_launch(void* const* d_in, const int* in_sizes, int n_in,
                              void* d_out, int out_size) {
    const float* x_phy  = (const float*)d_in[0];
    const float* params = (const float*)d_in[1];
    float* out = (float*)d_out;
    (void)in_sizes; (void)n_in; (void)out_size;
    hmets_kernel<<<(G_NUM + 31) / 32, 32>>>(x_phy, params, out);
}

// round 8
// speedup vs baseline: 4.5566x; 4.5566x over previous
#include <cuda_runtime.h>
#include <math.h>

static constexpr int T_STEPS = 1460;
static constexpr int G_NUM   = 5000;
static constexpr int UH_L    = 15;
static constexpr int PF      = 10;   // 1460 % 10 == 0

__global__ void __launch_bounds__(32) hmets_kernel(
    const float* __restrict__ x_phy,     // (T, G, 3)
    const float* __restrict__ params,    // (T, G, 20) -- only t = T-1 used
    float* __restrict__ out)             // (T, G)
{
    const int g = blockIdx.x * blockDim.x + threadIdx.x;
    if (g >= G_NUM) return;

    // ---------------- parameters ----------------
    const float* pp = params + ((long long)(T_STEPS - 1) * G_NUM + g) * 20;
    float r[20];
#pragma unroll
    for (int i = 0; i < 20; i++) r[i] = 1.0f / (1.0f + expf(-pp[i]));

    const float ddf_min = r[0]  * 20.0f;
    const float ddf_pls = r[1]  * 20.0f;
    const float Tbm     = -2.0f  + r[2]  * 5.0f;
    const float Kcum    = 0.01f  + r[3]  * 0.19f;
    const float fcmin   = r[4]  * 0.1f;
    const float fcminp  = 0.01f  + r[5]  * 0.24f;
    const float Ccum    = 0.005f + r[6]  * 0.045f;
    const float Tbf     = -5.0f  + r[7]  * 7.0f;
    const float Kf      = r[8]  * 5.0f;
    const float exp_fe  = r[9];
    const float ET_eff  = r[10] * 3.0f;
    const float c_run   = r[11];
    const float c_v2p   = 1e-5f  + r[12] * (0.02f - 1e-5f);
    const float c_vad   = r[13] * 0.1f;
    const float c_phr   = 1e-5f  + r[14] * (0.01f - 1e-5f);
    const float Vmax    = 0.001f + r[15] * (500.0f - 0.001f);

    const float a1 = 0.3f  + r[16] * (20.0f - 0.3f);
    const float b1 = 0.01f + r[17] * (5.0f  - 0.01f);
    const float a2 = 0.5f  + r[18] * (13.0f - 0.5f);
    const float b2 = 0.15f + r[19] * (1.5f  - 0.15f);

    // fused constants (off the critical path)
    const float ddf_cap = ddf_min + ddf_pls;
    const float ddfK    = ddf_min * Kcum;       // ddf = min(cap, fma(ddfK, C, ddf_min))
    const float fcsum   = fcmin + fcminp;
    const float nfcC    = -fcsum * Ccum;        // wrf = max(fma(C, nfcC, fcsum), fcmin)
    const float invVmax = 1.0f / Vmax;

    // ---------------- gamma unit hydrographs ----------------
    float uh1[UH_L], uh2[UH_L];
    {
        float s1 = 0.0f, s2 = 0.0f;
#pragma unroll
        for (int l = 0; l < UH_L; l++) {
            float tt = (float)l + 0.5f;
            float w1 = powf(tt, a1 - 1.0f) * expf(-tt / b1);
            float w2 = powf(tt, a2 - 1.0f) * expf(-tt / b2);
            uh1[l] = w1; uh2[l] = w2; s1 += w1; s2 += w2;
        }
        const float i1 = 1.0f / s1, i2 = 1.0f / s2;
#pragma unroll
        for (int l = 0; l < UH_L; l++) { uh1[l] *= i1; uh2[l] *= i2; }
    }

    // ---------------- state + conv shift-register ----------------
    float S = 1e-5f, W = 1e-5f, C = 1e-5f, V = 0.5f * Vmax, P = 1e-5f;
    float acc[UH_L];
#pragma unroll
    for (int l = 0; l < UH_L; l++) acc[l] = 0.0f;

    // ------- RAW forcing prefetch ring (load results ONLY -- nothing touches
    //         them at prefetch time, so the scoreboard wait lands PF steps later)
    const float* xb = x_phy + (long long)g * 3;
    float bp[PF], bt[PF], be[PF];
#pragma unroll
    for (int j = 0; j < PF; j++) {
        const float* q = xb + (long long)j * (3LL * G_NUM);
        bp[j] = q[0]; bt[j] = q[1]; be[j] = q[2];
    }
    float* ob = out + g;

    // ------- derived-value software pipeline (1 step ahead) -------
    // derived values for the CURRENT step, computed during the PREVIOUS step
    float d_rain, d_snow, d_potfr, d_mm, d_RET;
    {
        const float Pp = bp[0], Tt = bt[0], PE = be[0];
        d_rain  = (Tt >= 0.0f) ? Pp : 0.0f;
        d_snow  = (Tt <  0.0f) ? Pp : 0.0f;
        d_potfr = Kf * __powf(fmaxf(Tbf - Tt, 1e-5f), exp_fe);
        d_mm    = Tt - Tbm;
        d_RET   = ET_eff * PE;
    }

    for (int tb = 0; tb < T_STEPS; tb += PF) {
#pragma unroll
        for (int j = 0; j < PF; j++) {
            const int t = tb + j;

            // consume this step's derived values (ready since last iteration)
            const float rain = d_rain, snow = d_snow, potfr = d_potfr,
                        mm   = d_mm,   RET  = d_RET;

            // refill ring slot j with raw loads for step t+PF (no derivation!)
            if (t + PF < T_STEPS) {
                const float* q = xb + (long long)(t + PF) * (3LL * G_NUM);
                bp[j] = q[0]; bt[j] = q[1]; be[j] = q[2];
            }

            // derive NEXT step's values from ring slot (j+1)%PF
            // (raw values loaded PF steps ago -- register-resident, no mem stall;
            //  the __powf MUFU chain overlaps this step's state-update stalls)
            {
                const int jn = (j + 1 < PF) ? (j + 1) : 0;
                const float Pp = bp[jn], Tt = bt[jn], PE = be[jn];
                d_rain  = (Tt >= 0.0f) ? Pp : 0.0f;
                d_snow  = (Tt <  0.0f) ? Pp : 0.0f;
                d_potfr = Kf * __powf(fmaxf(Tbf - Tt, 1e-5f), exp_fe);
                d_mm    = Tt - Tbm;
                d_RET   = ET_eff * PE;
            }

            // -------- HMETS step, minimized critical path --------
            const float fr      = fminf(potfr, W);
            const float Wm      = W - fr;
            const float ddf     = fminf(ddf_cap, fmaf(ddfK, C, ddf_min));
            const float meltcap = fmaxf(ddf * mm, 0.0f);
            const float S1      = S + fr;
            const float Ssn     = S1 + snow;
            const float melt    = fminf(meltcap, Ssn);
            S = Ssn - melt;
            C = (S > 1e-5f) ? (C + melt) : 0.0f;

            const float wrf  = fmaxf(fmaf(C, nfcC, fcsum), fcmin);
            const float wr   = wrf * S;
            const float wtmp = Wm + melt + rain;
            const float wa   = fmaxf(wtmp - wr, 0.0f);
            W = fminf(wtmp, wr);          // == (wa>0 ? wr : wtmp), wr >= 0

            const float ratio = V * invVmax;      // parallel side-chain off V
            const float crr   = c_run * ratio;
            const float crr2  = crr * ratio;
            const float omc2  = 1.0f - crr2;
            const float ht2   = c_vad * V;
            const float v2p   = c_v2p * V;
            const float Vbase = (V - ht2) - v2p;

            const float ht0   = crr * wa;
            const float infil = fmaxf((wa - RET) - ht0, 0.0f);
            const float V2    = fmaf(infil, omc2, Vbase);  // V + (infil-ht1) - ht2 - v2p
            const float Vn    = fminf(V2, Vmax);
            const float over  = V2 - Vn;
            V = Vn;
            const float ht1   = fmaf(crr2, infil, over);   // ht1 + over

            P = P + v2p;
            const float ht3 = c_phr * P;
            P = P - ht3;

            // -------- fused UH convolution (scatter) + output --------
            ob[(long long)t * G_NUM] = acc[0] + ht0 * uh1[0] + ht1 * uh2[0] + (ht2 + ht3);
#pragma unroll
            for (int l = 0; l < UH_L - 1; l++)
                acc[l] = acc[l + 1] + ht0 * uh1[l + 1] + ht1 * uh2[l + 1];
            acc[UH_L - 1] = 0.0f;
        }
    }
}

extern "C" void kernel_launch(void* const* d_in, const int* in_sizes, int n_in,
                              void* d_out, int out_size) {
    const float* x_phy  = (const float*)d_in[0];
    const float* params = (const float*)d_in[1];
    float* out = (float*)d_out;
    (void)in_sizes; (void)n_in; (void)out_size;
    hmets_kernel<<<(G_NUM + 31) / 32, 32>>>(x_phy, params, out);
}